// round 14
// baseline (speedup 1.0000x reference)
#include <cuda_runtime.h>
#include <cuda_bf16.h>

#define NN 50000
#define EE 800000
#define DD 128
#define BB 100
#define LSLOPE 0.01f
typedef unsigned long long u64;
typedef unsigned int u32;
typedef unsigned short u16;

#define LDSM4(r0,r1,r2,r3,a) \
  asm volatile("ldmatrix.sync.aligned.m8n8.x4.shared.b16 {%0,%1,%2,%3}, [%4];" \
    : "=r"(r0),"=r"(r1),"=r"(r2),"=r"(r3) : "r"(a))

#define MMA16816(c, a0,a1,a2,a3, b0,b1) \
  asm volatile("mma.sync.aligned.m16n8k16.row.col.f32.bf16.bf16.f32 " \
    "{%0,%1,%2,%3}, {%4,%5,%6,%7}, {%8,%9}, {%0,%1,%2,%3};" \
    : "+f"((c)[0]),"+f"((c)[1]),"+f"((c)[2]),"+f"((c)[3]) \
    : "r"(a0),"r"(a1),"r"(a2),"r"(a3), "r"(b0),"r"(b1))

#define WST 136
#define TB  34816
#define TB64 17408

// ---------------- scratch ----------------
__device__ float d_aterm[NN*DD];
__device__ float d_bterm[NN*DD];
__device__ float d_c1[NN*DD];
__device__ float d_hfsum[NN*DD];
__device__ float d_npool[BB*DD];
__device__ float d_epool[BB*DD];
__device__ float d_gpool[BB*DD];
__device__ float d_gnew[BB*DD];
__device__ int   d_deg[NN];
__device__ int   d_nncnt[BB];
__device__ int   d_necnt[BB];
// 0=We 1=Weu3 2=Wn 3=Wg 4=Weu1 5=Weu2 6=Weu4 7=Wnu1 8=Wnu3 9=Wnu2
__device__ __align__(16) u16 d_wth[10][DD*WST];
__device__ __align__(16) u16 d_wtl[10][DD*WST];

__device__ __forceinline__ float lrelu(float x){ return x > 0.f ? x : LSLOPE*x; }

__device__ __forceinline__ void red4(float* p, float4 v){
  asm volatile("red.global.add.v4.f32 [%0], {%1, %2, %3, %4};"
               :: "l"(p), "f"(v.x), "f"(v.y), "f"(v.z), "f"(v.w) : "memory");
}
__device__ __forceinline__ void red2(float* p, float x, float y){
  asm volatile("red.global.add.v2.f32 [%0], {%1, %2};"
               :: "l"(p), "f"(x), "f"(y) : "memory");
}
__device__ __forceinline__ u32 smaddr(const void* p){
  u32 a; asm("{ .reg .u64 t; cvta.to.shared.u64 t, %1; cvt.u32.u64 %0, t; }" : "=r"(a) : "l"(p));
  return a;
}
__device__ __forceinline__ u32 pack_bf16(float a, float b){
  __nv_bfloat16 h0=__float2bfloat16(a), h1=__float2bfloat16(b);
  return ((u32)__bfloat16_as_ushort(h1)<<16)|__bfloat16_as_ushort(h0);
}
#define ZB4(acc) { _Pragma("unroll") for (int za=0; za<2; ++za) _Pragma("unroll") for (int zb=0; zb<4; ++zb) _Pragma("unroll") for (int zc=0; zc<4; ++zc) acc[za][zb][zc]=0.f; }

// FUSED 3-split pass: acc += AH@BH + AH@BL + AL@BH (2 m-tiles x 4 n-tiles per warp)
__device__ __forceinline__ void hpass3(u32 aH, u32 aL, u32 bH, u32 bL,
                                       float acc[2][4][4], int mbase, int nbase, int lane)
{
  int at = lane >> 3;
  int arow = (at & 1)*8 + (lane & 7);
  int acol = (at >> 1)*8;
  int bg = lane >> 3;
  int bn = (bg >> 1)*8 + (lane & 7);
  int bk = (bg & 1)*8;
  #pragma unroll
  for (int ks = 0; ks < 8; ++ks) {
    int k0 = ks*16;
    u32 ah[2][4], al[2][4];
    #pragma unroll
    for (int mt = 0; mt < 2; ++mt) {
      u32 off = (u32)(mbase + mt*16 + arow)*272 + (u32)(k0 + acol)*2;
      LDSM4(ah[mt][0],ah[mt][1],ah[mt][2],ah[mt][3], aH + off);
      LDSM4(al[mt][0],al[mt][1],al[mt][2],al[mt][3], aL + off);
    }
    u32 bh[4][2], bl[4][2];
    #pragma unroll
    for (int g = 0; g < 2; ++g) {
      u32 off = (u32)(nbase + g*16 + bn)*272 + (u32)(k0 + bk)*2;
      u32 r0,r1,r2,r3;
      LDSM4(r0,r1,r2,r3, bH + off);
      bh[g*2][0]=r0; bh[g*2][1]=r1; bh[g*2+1][0]=r2; bh[g*2+1][1]=r3;
      LDSM4(r0,r1,r2,r3, bL + off);
      bl[g*2][0]=r0; bl[g*2][1]=r1; bl[g*2+1][0]=r2; bl[g*2+1][1]=r3;
    }
    #pragma unroll
    for (int mt = 0; mt < 2; ++mt)
      #pragma unroll
      for (int nt = 0; nt < 4; ++nt) {
        MMA16816(acc[mt][nt], ah[mt][0],ah[mt][1],ah[mt][2],ah[mt][3], bh[nt][0],bh[nt][1]);
        MMA16816(acc[mt][nt], ah[mt][0],ah[mt][1],ah[mt][2],ah[mt][3], bl[nt][0],bl[nt][1]);
        MMA16816(acc[mt][nt], al[mt][0],al[mt][1],al[mt][2],al[mt][3], bh[nt][0],bh[nt][1]);
      }
  }
}

__device__ __forceinline__ void loadW(int widx, char* smx, int dH, int dL, int tid, int nthr){
  __syncthreads();
  for (int i = tid; i < DD*WST/8; i += nthr) {
    reinterpret_cast<uint4*>(smx + dH)[i] = reinterpret_cast<const uint4*>(d_wth[widx])[i];
    reinterpret_cast<uint4*>(smx + dL)[i] = reinterpret_cast<const uint4*>(d_wtl[widx])[i];
  }
  __syncthreads();
}

__global__ void kInit(){
  int idx = blockIdx.x*blockDim.x + threadIdx.x;
  if (idx < NN*DD) d_hfsum[idx] = 0.f;
  if (idx < BB*DD) { d_npool[idx]=0.f; d_epool[idx]=0.f; d_gpool[idx]=0.f; }
  if (idx < NN) d_deg[idx] = 0;
  if (idx < BB) { d_nncnt[idx]=0; d_necnt[idx]=0; }
}

__global__ void kCounts(const int* __restrict__ dst, const int* __restrict__ n2g){
  int idx = blockIdx.x*blockDim.x + threadIdx.x;
  if (idx < EE) atomicAdd(&d_deg[dst[idx]], 1);
  if (idx < NN) atomicAdd(&d_nncnt[n2g[idx]], 1);
}

__global__ void kW(const float* __restrict__ We, const float* __restrict__ Weu,
                   const float* __restrict__ Wn, const float* __restrict__ Wg,
                   const float* __restrict__ Wnu){
  int k = blockIdx.x, w = blockIdx.y, n = threadIdx.x;
  const float* src;
  switch (w) {
    case 0: src = We; break;
    case 1: src = Weu + 256*DD; break;
    case 2: src = Wn; break;
    case 3: src = Wg; break;
    case 4: src = Weu; break;
    case 5: src = Weu + 128*DD; break;
    case 6: src = Weu + 384*DD; break;
    case 7: src = Wnu; break;
    case 8: src = Wnu + 256*DD; break;
    default: src = Wnu + 128*DD; break;   // 9 = Wnu2
  }
  float v = src[k*DD + n];
  __nv_bfloat16 hi = __float2bfloat16(v);
  __nv_bfloat16 lo = __float2bfloat16(v - __bfloat162float(hi));
  d_wth[w][n*WST + k] = __bfloat16_as_ushort(hi);
  d_wtl[w][n*WST + k] = __bfloat16_as_ushort(lo);
}

// ---- kA: fused HMMA per-node precompute (512 threads, dual weight buffers) ----
#define A_HH 0
#define A_HL TB
#define A_UH (2*TB)
#define A_UL (3*TB)
#define A_W0 (4*TB)
#define A_W1 (5*TB)
#define A_BI (6*TB)
#define SMA_T (6*TB + 2048)

__global__ __launch_bounds__(512, 1) void kA(
    const float* __restrict__ node, const float* __restrict__ graph,
    const float* __restrict__ bn, const float* __restrict__ bg,
    const float* __restrict__ beu, const float* __restrict__ bnu)
{
  extern __shared__ __align__(16) char smx[];
  float* sBn  = (float*)(smx + A_BI);
  float* sBg  = sBn + DD;
  float* sBeu = sBg + DD;
  float* sBnu = sBeu + DD;
  u32 sbase = smaddr(smx);
  int tid = threadIdx.x, lane = tid & 31, wid = tid >> 5;
  int mbase = (wid & 3)*32, nbase = (wid >> 2)*32;
  int row0 = blockIdx.x * 128;
  int qrow = lane >> 2, qcol = lane & 3;
  u32 w0 = sbase + A_W0, w1 = sbase + A_W1;

  if (tid < DD) { sBn[tid]=bn[tid]; sBg[tid]=bg[tid]; sBeu[tid]=beu[tid]; sBnu[tid]=bnu[tid]; }

  #pragma unroll 2
  for (int it = 0; it < 8; ++it) {
    int i = tid + it*512;
    int r = i >> 5, q = i & 31;
    int n = row0 + r;
    float4 v = make_float4(0,0,0,0), g = v;
    if (n < NN) {
      v = reinterpret_cast<const float4*>(node)[(size_t)n*32 + q];
      g = reinterpret_cast<const float4*>(graph)[(size_t)n*32 + q];
    }
    u32 off = (u32)r*272 + (u32)q*8;
    *reinterpret_cast<uint2*>(smx + A_HH + off) = make_uint2(pack_bf16(v.x,v.y), pack_bf16(v.z,v.w));
    float lx=v.x-__bfloat162float(__float2bfloat16(v.x)), ly=v.y-__bfloat162float(__float2bfloat16(v.y));
    float lz=v.z-__bfloat162float(__float2bfloat16(v.z)), lw=v.w-__bfloat162float(__float2bfloat16(v.w));
    *reinterpret_cast<uint2*>(smx + A_HL + off) = make_uint2(pack_bf16(lx,ly), pack_bf16(lz,lw));
    *reinterpret_cast<uint2*>(smx + A_UH + off) = make_uint2(pack_bf16(g.x,g.y), pack_bf16(g.z,g.w));
    lx=g.x-__bfloat162float(__float2bfloat16(g.x)); ly=g.y-__bfloat162float(__float2bfloat16(g.y));
    lz=g.z-__bfloat162float(__float2bfloat16(g.z)); lw=g.w-__bfloat162float(__float2bfloat16(g.w));
    *reinterpret_cast<uint2*>(smx + A_UL + off) = make_uint2(pack_bf16(lx,ly), pack_bf16(lz,lw));
  }

  float acc[2][4][4];

  // h = lrelu(node@Wn + bn)
  ZB4(acc);
  loadW(2, smx, A_W0, A_W1, tid, 512);
  hpass3(sbase+A_HH, sbase+A_HL, w0, w1, acc, mbase, nbase, lane);
  __syncthreads();
  #pragma unroll
  for (int mt=0; mt<2; ++mt)
    #pragma unroll
    for (int hr=0; hr<2; ++hr) {
      int row = mbase + mt*16 + qrow + hr*8;
      #pragma unroll
      for (int nt=0; nt<4; ++nt) {
        int c = nbase + nt*8 + qcol*2;
        float f0 = lrelu(acc[mt][nt][hr*2] + sBn[c]);
        float f1 = lrelu(acc[mt][nt][hr*2+1] + sBn[c+1]);
        __nv_bfloat16 h0=__float2bfloat16(f0), h1=__float2bfloat16(f1);
        u32 off = (u32)row*272 + (u32)c*2;
        *reinterpret_cast<u32*>(smx + A_HH + off) = ((u32)__bfloat16_as_ushort(h1)<<16)|__bfloat16_as_ushort(h0);
        *reinterpret_cast<u32*>(smx + A_HL + off) = pack_bf16(f0-__bfloat162float(h0), f1-__bfloat162float(h1));
      }
    }

  // u = lrelu(graph@Wg + bg)
  ZB4(acc);
  loadW(3, smx, A_W0, A_W1, tid, 512);
  hpass3(sbase+A_UH, sbase+A_UL, w0, w1, acc, mbase, nbase, lane);
  __syncthreads();
  #pragma unroll
  for (int mt=0; mt<2; ++mt)
    #pragma unroll
    for (int hr=0; hr<2; ++hr) {
      int row = mbase + mt*16 + qrow + hr*8;
      #pragma unroll
      for (int nt=0; nt<4; ++nt) {
        int c = nbase + nt*8 + qcol*2;
        float f0 = lrelu(acc[mt][nt][hr*2] + sBg[c]);
        float f1 = lrelu(acc[mt][nt][hr*2+1] + sBg[c+1]);
        __nv_bfloat16 h0=__float2bfloat16(f0), h1=__float2bfloat16(f1);
        u32 off = (u32)row*272 + (u32)c*2;
        *reinterpret_cast<u32*>(smx + A_UH + off) = ((u32)__bfloat16_as_ushort(h1)<<16)|__bfloat16_as_ushort(h0);
        *reinterpret_cast<u32*>(smx + A_UL + off) = pack_bf16(f0-__bfloat162float(h0), f1-__bfloat162float(h1));
      }
    }

  // aterm = h@Weu1
  ZB4(acc);
  loadW(4, smx, A_W0, A_W1, tid, 512);
  hpass3(sbase+A_HH, sbase+A_HL, w0, w1, acc, mbase, nbase, lane);
  #pragma unroll
  for (int mt=0; mt<2; ++mt)
    #pragma unroll
    for (int hr=0; hr<2; ++hr) {
      int row = mbase + mt*16 + qrow + hr*8;
      int n = row0 + row; if (n >= NN) continue;
      #pragma unroll
      for (int nt=0; nt<4; ++nt) {
        int c = nbase + nt*8 + qcol*2;
        *reinterpret_cast<float2*>(d_aterm + (size_t)n*DD + c) =
          make_float2(acc[mt][nt][hr*2], acc[mt][nt][hr*2+1]);
      }
    }

  // bterm = h@Weu2 + u@Weu4 + beu
  ZB4(acc);
  loadW(5, smx, A_W0, A_W1, tid, 512);
  hpass3(sbase+A_HH, sbase+A_HL, w0, w1, acc, mbase, nbase, lane);
  loadW(6, smx, A_W0, A_W1, tid, 512);
  hpass3(sbase+A_UH, sbase+A_UL, w0, w1, acc, mbase, nbase, lane);
  #pragma unroll
  for (int mt=0; mt<2; ++mt)
    #pragma unroll
    for (int hr=0; hr<2; ++hr) {
      int row = mbase + mt*16 + qrow + hr*8;
      int n = row0 + row; if (n >= NN) continue;
      #pragma unroll
      for (int nt=0; nt<4; ++nt) {
        int c = nbase + nt*8 + qcol*2;
        *reinterpret_cast<float2*>(d_bterm + (size_t)n*DD + c) =
          make_float2(acc[mt][nt][hr*2] + sBeu[c], acc[mt][nt][hr*2+1] + sBeu[c+1]);
      }
    }

  // c1 = h@Wnu1 + u@Wnu3 + bnu
  ZB4(acc);
  loadW(7, smx, A_W0, A_W1, tid, 512);
  hpass3(sbase+A_HH, sbase+A_HL, w0, w1, acc, mbase, nbase, lane);
  loadW(8, smx, A_W0, A_W1, tid, 512);
  hpass3(sbase+A_UH, sbase+A_UL, w0, w1, acc, mbase, nbase, lane);
  #pragma unroll
  for (int mt=0; mt<2; ++mt)
    #pragma unroll
    for (int hr=0; hr<2; ++hr) {
      int row = mbase + mt*16 + qrow + hr*8;
      int n = row0 + row; if (n >= NN) continue;
      #pragma unroll
      for (int nt=0; nt<4; ++nt) {
        int c = nbase + nt*8 + qcol*2;
        *reinterpret_cast<float2*>(d_c1 + (size_t)n*DD + c) =
          make_float2(acc[mt][nt][hr*2] + sBnu[c], acc[mt][nt][hr*2+1] + sBnu[c+1]);
      }
    }
}

// ---- kB: 64-edge tiles, 256 threads, FORCED 2 blocks/SM ----
#define B_AH 0
#define B_AL TB64
#define B_WH (2*TB64)
#define B_WL (2*TB64 + TB)
#define B_BE (2*TB64 + 2*TB)
#define B_SRC (B_BE + 512)
#define B_DST (B_SRC + 256)
#define SMB_T (B_DST + 256)

__global__ __launch_bounds__(256, 2) void kB(
    const float* __restrict__ edge, const int* __restrict__ src, const int* __restrict__ dst,
    const float* __restrict__ be, float* __restrict__ out_edge)
{
  extern __shared__ __align__(16) char smx[];
  float* sBe = (float*)(smx + B_BE);
  int* sSrc = (int*)(smx + B_SRC);
  int* sDst = (int*)(smx + B_DST);
  u32 sbase = smaddr(smx);

  int tid = threadIdx.x, lane = tid & 31, wid = tid >> 5;
  int mbase = (wid & 1)*32, nbase = (wid >> 1)*32;
  long row0 = (long)blockIdx.x * 64;
  int qrow = lane >> 2, qcol = lane & 3;

  if (tid < DD) sBe[tid] = be[tid];
  if (tid < 64) { sSrc[tid] = src[row0 + tid]; sDst[tid] = dst[row0 + tid]; }

  for (int i = tid; i < DD*WST/8; i += 256) {
    reinterpret_cast<uint4*>(smx + B_WH)[i] = reinterpret_cast<const uint4*>(d_wth[0])[i];
    reinterpret_cast<uint4*>(smx + B_WL)[i] = reinterpret_cast<const uint4*>(d_wtl[0])[i];
  }
  #pragma unroll 2
  for (int it = 0; it < 8; ++it) {
    int i = tid + it*256;
    int r = i >> 5, q = i & 31;
    float4 v = reinterpret_cast<const float4*>(edge)[row0*32 + i];
    u32 off = (u32)r*272 + (u32)q*8;
    *reinterpret_cast<uint2*>(smx + B_AH + off) = make_uint2(pack_bf16(v.x,v.y), pack_bf16(v.z,v.w));
    float lx=v.x-__bfloat162float(__float2bfloat16(v.x)), ly=v.y-__bfloat162float(__float2bfloat16(v.y));
    float lz=v.z-__bfloat162float(__float2bfloat16(v.z)), lw=v.w-__bfloat162float(__float2bfloat16(v.w));
    *reinterpret_cast<uint2*>(smx + B_AL + off) = make_uint2(pack_bf16(lx,ly), pack_bf16(lz,lw));
  }
  __syncthreads();

  float acc[2][4][4];

  ZB4(acc);
  hpass3(sbase+B_AH, sbase+B_AL, sbase+B_WH, sbase+B_WL, acc, mbase, nbase, lane);
  __syncthreads();

  #pragma unroll
  for (int mt=0; mt<2; ++mt)
    #pragma unroll
    for (int hr=0; hr<2; ++hr) {
      int row = mbase + mt*16 + qrow + hr*8;
      #pragma unroll
      for (int nt=0; nt<4; ++nt) {
        int c = nbase + nt*8 + qcol*2;
        float f0 = lrelu(acc[mt][nt][hr*2] + sBe[c]);
        float f1 = lrelu(acc[mt][nt][hr*2+1] + sBe[c+1]);
        __nv_bfloat16 h0=__float2bfloat16(f0), h1=__float2bfloat16(f1);
        u32 off = (u32)row*272 + (u32)c*2;
        *reinterpret_cast<u32*>(smx + B_AH + off) = ((u32)__bfloat16_as_ushort(h1)<<16)|__bfloat16_as_ushort(h0);
        *reinterpret_cast<u32*>(smx + B_AL + off) = pack_bf16(f0-__bfloat162float(h0), f1-__bfloat162float(h1));
      }
    }
  for (int i = tid; i < DD*WST/8; i += 256) {
    reinterpret_cast<uint4*>(smx + B_WH)[i] = reinterpret_cast<const uint4*>(d_wth[1])[i];
    reinterpret_cast<uint4*>(smx + B_WL)[i] = reinterpret_cast<const uint4*>(d_wtl[1])[i];
  }
  __syncthreads();

  ZB4(acc);
  hpass3(sbase+B_AH, sbase+B_AL, sbase+B_WH, sbase+B_WL, acc, mbase, nbase, lane);

  #pragma unroll
  for (int mt=0; mt<2; ++mt)
    #pragma unroll
    for (int hr=0; hr<2; ++hr) {
      int row = mbase + mt*16 + qrow + hr*8;
      long e = row0 + row;
      int s = sSrc[row], d = sDst[row];
      float2 a2[4], b2[4], er[4];
      #pragma unroll
      for (int nt=0; nt<4; ++nt) {
        int c = nbase + nt*8 + qcol*2;
        a2[nt] = *reinterpret_cast<const float2*>(d_aterm + (size_t)s*DD + c);
        b2[nt] = *reinterpret_cast<const float2*>(d_bterm + (size_t)d*DD + c);
        er[nt] = *reinterpret_cast<const float2*>(edge + (size_t)e*DD + c);
      }
      #pragma unroll
      for (int nt=0; nt<4; ++nt) {
        int c = nbase + nt*8 + qcol*2;
        float f0 = lrelu(acc[mt][nt][hr*2]   + a2[nt].x + b2[nt].x);
        float f1 = lrelu(acc[mt][nt][hr*2+1] + a2[nt].y + b2[nt].y);
        *reinterpret_cast<float2*>(out_edge + (size_t)e*DD + c) = make_float2(f0+er[nt].x, f1+er[nt].y);
        red2(d_hfsum + (size_t)d*DD + c, f0, f1);
      }
    }
}

// ---- kC: fused HMMA node update (64 nodes/block, 256 threads, 2 blocks/SM) ----
#define C_HH 0
#define C_HL TB64
#define C_WH (2*TB64)
#define C_WL (2*TB64 + TB)
#define C_AUX (2*TB64 + 2*TB)
#define SMC_T (C_AUX + 512)

__global__ __launch_bounds__(256, 2) void kC(
    const float* __restrict__ node, const float* __restrict__ graph,
    const int* __restrict__ n2g, float* __restrict__ out_node)
{
  extern __shared__ __align__(16) char smx[];
  int*   sG = (int*)(smx + C_AUX);
  float* sD = (float*)(smx + C_AUX + 256);
  u32 sbase = smaddr(smx);
  int tid = threadIdx.x, lane = tid & 31, wid = tid >> 5;
  int mbase = (wid & 1)*32, nbase = (wid >> 1)*32;
  int row0 = blockIdx.x * 64;
  int qrow = lane >> 2, qcol = lane & 3;

  if (tid < 64) {
    int n = row0 + tid, g = 0, dg = 0;
    if (n < NN) { g = n2g[n]; dg = d_deg[n]; atomicAdd(&d_necnt[g], dg); }
    sG[tid] = g;
    sD[tid] = 1.f / fmaxf((float)dg, 1.f);
  }
  for (int i = tid; i < DD*WST/8; i += 256) {
    reinterpret_cast<uint4*>(smx + C_WH)[i] = reinterpret_cast<const uint4*>(d_wth[9])[i];
    reinterpret_cast<uint4*>(smx + C_WL)[i] = reinterpret_cast<const uint4*>(d_wtl[9])[i];
  }
  __syncthreads();

  // pooling + deg-scale + bf16 convert
  #pragma unroll 2
  for (int it = 0; it < 8; ++it) {
    int i = tid + it*256;
    int r = i >> 5, q = i & 31;
    int n = row0 + r;
    float4 h = make_float4(0,0,0,0);
    if (n < NN) {
      h = reinterpret_cast<const float4*>(d_hfsum)[(size_t)n*32 + q];
      int g = sG[r];
      red4(d_epool + g*DD + q*4, h);
      float4 gr = reinterpret_cast<const float4*>(graph)[(size_t)n*32 + q];
      red4(d_gpool + g*DD + q*4, gr);
      float rd = sD[r];
      h.x*=rd; h.y*=rd; h.z*=rd; h.w*=rd;
    }
    u32 off = (u32)r*272 + (u32)q*8;
    *reinterpret_cast<uint2*>(smx + C_HH + off) = make_uint2(pack_bf16(h.x,h.y), pack_bf16(h.z,h.w));
    float lx=h.x-__bfloat162float(__float2bfloat16(h.x)), ly=h.y-__bfloat162float(__float2bfloat16(h.y));
    float lz=h.z-__bfloat162float(__float2bfloat16(h.z)), lw=h.w-__bfloat162float(__float2bfloat16(h.w));
    *reinterpret_cast<uint2*>(smx + C_HL + off) = make_uint2(pack_bf16(lx,ly), pack_bf16(lz,lw));
  }
  __syncthreads();

  float acc[2][4][4];
  ZB4(acc);
  hpass3(sbase+C_HH, sbase+C_HL, sbase+C_WH, sbase+C_WL, acc, mbase, nbase, lane);

  // epilogue: node_new = lrelu(D + c1); out_node = node_new + node; npool += node_new
  #pragma unroll
  for (int mt=0; mt<2; ++mt)
    #pragma unroll
    for (int hr=0; hr<2; ++hr) {
      int row = mbase + mt*16 + qrow + hr*8;
      int n = row0 + row; if (n >= NN) continue;
      int g = sG[row];
      float2 c2[4], nr[4];
      #pragma unroll
      for (int nt=0; nt<4; ++nt) {
        int c = nbase + nt*8 + qcol*2;
        c2[nt] = *reinterpret_cast<const float2*>(d_c1 + (size_t)n*DD + c);
        nr[nt] = *reinterpret_cast<const float2*>(node + (size_t)n*DD + c);
      }
      #pragma unroll
      for (int nt=0; nt<4; ++nt) {
        int c = nbase + nt*8 + qcol*2;
        float f0 = lrelu(acc[mt][nt][hr*2]   + c2[nt].x);
        float f1 = lrelu(acc[mt][nt][hr*2+1] + c2[nt].y);
        *reinterpret_cast<float2*>(out_node + (size_t)n*DD + c) = make_float2(f0+nr[nt].x, f1+nr[nt].y);
        red2(d_npool + g*DD + c, f0, f1);
      }
    }
}

__global__ void kD(const float* __restrict__ Wnu, const float* __restrict__ bnu){
  __shared__ float sp[3*DD];
  int g = blockIdx.x, j = threadIdx.x;
  float rn = 1.f / fmaxf((float)d_nncnt[g], 1.f);
  float re = 1.f / fmaxf((float)d_necnt[g], 1.f);
  sp[j]      = d_npool[g*DD+j]*rn;
  sp[DD+j]   = d_epool[g*DD+j]*re;
  sp[2*DD+j] = d_gpool[g*DD+j]*rn;
  __syncthreads();
  float a = bnu[j];
  #pragma unroll 4
  for (int k = 0; k < 3*DD; ++k) a = fmaf(sp[k], Wnu[k*DD+j], a);
  d_gnew[g*DD+j] = lrelu(a);
}

__global__ void kE(const float* __restrict__ graph, const int* __restrict__ n2g,
                   float* __restrict__ out_graph){
  int t = blockIdx.x*blockDim.x + threadIdx.x;
  if (t >= NN*32) return;
  int n = t >> 5, q = t & 31;
  int g = n2g[n];
  float4 gv = reinterpret_cast<const float4*>(d_gnew)[g*32 + q];
  float4 rv = reinterpret_cast<const float4*>(graph)[(size_t)n*32 + q];
  reinterpret_cast<float4*>(out_graph)[t] = make_float4(gv.x+rv.x, gv.y+rv.y, gv.z+rv.z, gv.w+rv.w);
}

extern "C" void kernel_launch(void* const* d_in, const int* in_sizes, int n_in,
                              void* d_out, int out_size) {
  const float* node  = (const float*)d_in[0];
  const float* edge  = (const float*)d_in[1];
  const float* graph = (const float*)d_in[2];
  const int*   src   = (const int*)d_in[3];
  const int*   dst   = (const int*)d_in[4];
  const int*   n2g   = (const int*)d_in[5];
  const float* Wn  = (const float*)d_in[6];
  const float* bn  = (const float*)d_in[7];
  const float* We  = (const float*)d_in[8];
  const float* be  = (const float*)d_in[9];
  const float* Wg  = (const float*)d_in[10];
  const float* bg  = (const float*)d_in[11];
  const float* Weu = (const float*)d_in[12];
  const float* beu = (const float*)d_in[13];
  const float* Wnu = (const float*)d_in[14];
  const float* bnu = (const float*)d_in[15];
  float* out_node  = (float*)d_out;
  float* out_edge  = out_node + (size_t)NN*DD;
  float* out_graph = out_edge + (size_t)EE*DD;

  cudaFuncSetAttribute(kA, cudaFuncAttributeMaxDynamicSharedMemorySize, SMA_T);
  cudaFuncSetAttribute(kB, cudaFuncAttributeMaxDynamicSharedMemorySize, SMB_T);
  cudaFuncSetAttribute(kC, cudaFuncAttributeMaxDynamicSharedMemorySize, SMC_T);

  kInit<<<(NN*DD + 255)/256, 256>>>();
  kCounts<<<(EE + 255)/256, 256>>>(dst, n2g);
  kW<<<dim3(128, 10), 128>>>(We, Weu, Wn, Wg, Wnu);
  kA<<<(NN + 127)/128, 512, SMA_T>>>(node, graph, bn, bg, beu, bnu);
  kB<<<EE/64, 256, SMB_T>>>(edge, src, dst, be, out_edge);
  kC<<<(NN + 63)/64, 256, SMC_T>>>(node, graph, n2g, out_node);
  kD<<<BB, DD>>>(Wnu, bnu);
  kE<<<(NN*32 + 255)/256, 256>>>(graph, n2g, out_graph);
}

// round 15
// speedup vs baseline: 1.0286x; 1.0286x over previous
#include <cuda_runtime.h>
#include <cuda_bf16.h>

#define NN 50000
#define EE 800000
#define DD 128
#define BB 100
#define LSLOPE 0.01f
typedef unsigned long long u64;
typedef unsigned int u32;
typedef unsigned short u16;

#define FMA2(d,a,b,c) asm("fma.rn.f32x2 %0, %1, %2, %3;" : "=l"(d) : "l"(a), "l"(b), "l"(c))
#define PACK2(d,x)    asm("mov.b64 %0, {%1, %1};" : "=l"(d) : "r"(__float_as_uint(x)))
#define UNPK2(lo,hi,v) asm("mov.b64 {%0, %1}, %2;" : "=r"(lo), "=r"(hi) : "l"(v))

#define LDSM4(r0,r1,r2,r3,a) \
  asm volatile("ldmatrix.sync.aligned.m8n8.x4.shared.b16 {%0,%1,%2,%3}, [%4];" \
    : "=r"(r0),"=r"(r1),"=r"(r2),"=r"(r3) : "r"(a))

#define MMA16816(c, a0,a1,a2,a3, b0,b1) \
  asm volatile("mma.sync.aligned.m16n8k16.row.col.f32.bf16.bf16.f32 " \
    "{%0,%1,%2,%3}, {%4,%5,%6,%7}, {%8,%9}, {%0,%1,%2,%3};" \
    : "+f"((c)[0]),"+f"((c)[1]),"+f"((c)[2]),"+f"((c)[3]) \
    : "r"(a0),"r"(a1),"r"(a2),"r"(a3), "r"(b0),"r"(b1))

#define WST 136
#define TB  34816
#define TB64 17408

// ---------------- scratch ----------------
__device__ float d_aterm[NN*DD];
__device__ float d_bterm[NN*DD];
__device__ float d_c1[NN*DD];
__device__ float d_hfsum[NN*DD];
__device__ float d_npool[BB*DD];
__device__ float d_epool[BB*DD];
__device__ float d_gpool[BB*DD];
__device__ float d_gnew[BB*DD];
__device__ int   d_deg[NN];
__device__ int   d_nncnt[BB];
__device__ int   d_necnt[BB];
// 0=We 1=Weu3 2=Wn 3=Wg 4=Weu1 5=Weu2 6=Weu4 7=Wnu1 8=Wnu3
__device__ __align__(16) u16 d_wth[9][DD*WST];
__device__ __align__(16) u16 d_wtl[9][DD*WST];

__device__ __forceinline__ float lrelu(float x){ return x > 0.f ? x : LSLOPE*x; }

__device__ __forceinline__ void red4(float* p, float4 v){
  asm volatile("red.global.add.v4.f32 [%0], {%1, %2, %3, %4};"
               :: "l"(p), "f"(v.x), "f"(v.y), "f"(v.z), "f"(v.w) : "memory");
}
__device__ __forceinline__ void red2(float* p, float x, float y){
  asm volatile("red.global.add.v2.f32 [%0], {%1, %2};"
               :: "l"(p), "f"(x), "f"(y) : "memory");
}
__device__ __forceinline__ u32 smaddr(const void* p){
  u32 a; asm("{ .reg .u64 t; cvta.to.shared.u64 t, %1; cvt.u32.u64 %0, t; }" : "=r"(a) : "l"(p));
  return a;
}
__device__ __forceinline__ u32 pack_bf16(float a, float b){
  __nv_bfloat16 h0=__float2bfloat16(a), h1=__float2bfloat16(b);
  return ((u32)__bfloat16_as_ushort(h1)<<16)|__bfloat16_as_ushort(h0);
}
__device__ __forceinline__ void unpack_acc(const u64* a, float* v){
  unsigned lo, hi;
  UNPK2(lo,hi,a[0]); v[0]=__uint_as_float(lo); v[1]=__uint_as_float(hi);
  UNPK2(lo,hi,a[1]); v[2]=__uint_as_float(lo); v[3]=__uint_as_float(hi);
  UNPK2(lo,hi,a[2]); v[4]=__uint_as_float(lo); v[5]=__uint_as_float(hi);
  UNPK2(lo,hi,a[3]); v[6]=__uint_as_float(lo); v[7]=__uint_as_float(hi);
}
#define ZACC4(acc) { _Pragma("unroll") for (int zi=0; zi<4; ++zi){ _Pragma("unroll") for (int zj=0; zj<4; ++zj) acc[zi][zj]=0ull; } }
#define ZB4(acc) { _Pragma("unroll") for (int za=0; za<2; ++za) _Pragma("unroll") for (int zb=0; zb<4; ++zb) _Pragma("unroll") for (int zc=0; zc<4; ++zc) acc[za][zb][zc]=0.f; }

// FUSED 3-split pass: acc += AH@BH + AH@BL + AL@BH (2 m-tiles x 4 n-tiles per warp)
__device__ __forceinline__ void hpass3(u32 aH, u32 aL, u32 bH, u32 bL,
                                       float acc[2][4][4], int mbase, int nbase, int lane)
{
  int at = lane >> 3;
  int arow = (at & 1)*8 + (lane & 7);
  int acol = (at >> 1)*8;
  int bg = lane >> 3;
  int bn = (bg >> 1)*8 + (lane & 7);
  int bk = (bg & 1)*8;
  #pragma unroll
  for (int ks = 0; ks < 8; ++ks) {
    int k0 = ks*16;
    u32 ah[2][4], al[2][4];
    #pragma unroll
    for (int mt = 0; mt < 2; ++mt) {
      u32 off = (u32)(mbase + mt*16 + arow)*272 + (u32)(k0 + acol)*2;
      LDSM4(ah[mt][0],ah[mt][1],ah[mt][2],ah[mt][3], aH + off);
      LDSM4(al[mt][0],al[mt][1],al[mt][2],al[mt][3], aL + off);
    }
    u32 bh[4][2], bl[4][2];
    #pragma unroll
    for (int g = 0; g < 2; ++g) {
      u32 off = (u32)(nbase + g*16 + bn)*272 + (u32)(k0 + bk)*2;
      u32 r0,r1,r2,r3;
      LDSM4(r0,r1,r2,r3, bH + off);
      bh[g*2][0]=r0; bh[g*2][1]=r1; bh[g*2+1][0]=r2; bh[g*2+1][1]=r3;
      LDSM4(r0,r1,r2,r3, bL + off);
      bl[g*2][0]=r0; bl[g*2][1]=r1; bl[g*2+1][0]=r2; bl[g*2+1][1]=r3;
    }
    #pragma unroll
    for (int mt = 0; mt < 2; ++mt)
      #pragma unroll
      for (int nt = 0; nt < 4; ++nt) {
        MMA16816(acc[mt][nt], ah[mt][0],ah[mt][1],ah[mt][2],ah[mt][3], bh[nt][0],bh[nt][1]);
        MMA16816(acc[mt][nt], ah[mt][0],ah[mt][1],ah[mt][2],ah[mt][3], bl[nt][0],bl[nt][1]);
        MMA16816(acc[mt][nt], al[mt][0],al[mt][1],al[mt][2],al[mt][3], bh[nt][0],bh[nt][1]);
      }
  }
}

__device__ __forceinline__ void loadW(int widx, char* smx, int dH, int dL, int tid, int nthr){
  __syncthreads();
  for (int i = tid; i < DD*WST/8; i += nthr) {
    reinterpret_cast<uint4*>(smx + dH)[i] = reinterpret_cast<const uint4*>(d_wth[widx])[i];
    reinterpret_cast<uint4*>(smx + dL)[i] = reinterpret_cast<const uint4*>(d_wtl[widx])[i];
  }
  __syncthreads();
}

// SIMT 64-row GEMM (kC)
__device__ __forceinline__ void mm_pass(const float* As, const float* __restrict__ W,
                                        u64 acc[4][4], float* Bs, int ty, int tx, int tid)
{
  #pragma unroll 1
  for (int k0 = 0; k0 < 128; k0 += 16) {
    __syncthreads();
    { int kr = tid >> 4, cc = (tid & 15) << 3;
      const float4* s4 = reinterpret_cast<const float4*>(W + (k0 + kr)*DD + cc);
      float4* t4 = reinterpret_cast<float4*>(Bs + kr*DD + cc);
      t4[0] = s4[0]; t4[1] = s4[1];
    }
    __syncthreads();
    #pragma unroll 4
    for (int k = 0; k < 16; ++k) {
      const float* br = Bs + k*DD;
      u64 b0 = *reinterpret_cast<const u64*>(br + tx*4);
      u64 b1 = *reinterpret_cast<const u64*>(br + tx*4 + 2);
      u64 b2 = *reinterpret_cast<const u64*>(br + 64 + tx*4);
      u64 b3 = *reinterpret_cast<const u64*>(br + 64 + tx*4 + 2);
      #pragma unroll
      for (int i = 0; i < 4; ++i) {
        u64 aa; PACK2(aa, As[(ty*4 + i)*DD + k0 + k]);
        FMA2(acc[i][0], aa, b0, acc[i][0]);
        FMA2(acc[i][1], aa, b1, acc[i][1]);
        FMA2(acc[i][2], aa, b2, acc[i][2]);
        FMA2(acc[i][3], aa, b3, acc[i][3]);
      }
    }
  }
}

__global__ void kInit(){
  int idx = blockIdx.x*blockDim.x + threadIdx.x;
  if (idx < NN*DD) d_hfsum[idx] = 0.f;
  if (idx < BB*DD) { d_npool[idx]=0.f; d_epool[idx]=0.f; d_gpool[idx]=0.f; }
  if (idx < NN) d_deg[idx] = 0;
  if (idx < BB) { d_nncnt[idx]=0; d_necnt[idx]=0; }
}

__global__ void kCounts(const int* __restrict__ dst, const int* __restrict__ n2g){
  int idx = blockIdx.x*blockDim.x + threadIdx.x;
  if (idx < EE) atomicAdd(&d_deg[dst[idx]], 1);
  if (idx < NN) atomicAdd(&d_nncnt[n2g[idx]], 1);
}

__global__ void kW(const float* __restrict__ We, const float* __restrict__ Weu,
                   const float* __restrict__ Wn, const float* __restrict__ Wg,
                   const float* __restrict__ Wnu){
  int k = blockIdx.x, w = blockIdx.y, n = threadIdx.x;
  const float* src;
  switch (w) {
    case 0: src = We; break;
    case 1: src = Weu + 256*DD; break;
    case 2: src = Wn; break;
    case 3: src = Wg; break;
    case 4: src = Weu; break;
    case 5: src = Weu + 128*DD; break;
    case 6: src = Weu + 384*DD; break;
    case 7: src = Wnu; break;
    default: src = Wnu + 256*DD; break;
  }
  float v = src[k*DD + n];
  __nv_bfloat16 hi = __float2bfloat16(v);
  __nv_bfloat16 lo = __float2bfloat16(v - __bfloat162float(hi));
  d_wth[w][n*WST + k] = __bfloat16_as_ushort(hi);
  d_wtl[w][n*WST + k] = __bfloat16_as_ushort(lo);
}

// ---- kA: fused HMMA per-node precompute (512 threads, dual weight buffers) ----
#define A_HH 0
#define A_HL TB
#define A_UH (2*TB)
#define A_UL (3*TB)
#define A_W0 (4*TB)
#define A_W1 (5*TB)
#define A_BI (6*TB)
#define SMA_T (6*TB + 2048)

__global__ __launch_bounds__(512, 1) void kA(
    const float* __restrict__ node, const float* __restrict__ graph,
    const float* __restrict__ bn, const float* __restrict__ bg,
    const float* __restrict__ beu, const float* __restrict__ bnu)
{
  extern __shared__ __align__(16) char smx[];
  float* sBn  = (float*)(smx + A_BI);
  float* sBg  = sBn + DD;
  float* sBeu = sBg + DD;
  float* sBnu = sBeu + DD;
  u32 sbase = smaddr(smx);
  int tid = threadIdx.x, lane = tid & 31, wid = tid >> 5;
  int mbase = (wid & 3)*32, nbase = (wid >> 2)*32;
  int row0 = blockIdx.x * 128;
  int qrow = lane >> 2, qcol = lane & 3;
  u32 w0 = sbase + A_W0, w1 = sbase + A_W1;

  if (tid < DD) { sBn[tid]=bn[tid]; sBg[tid]=bg[tid]; sBeu[tid]=beu[tid]; sBnu[tid]=bnu[tid]; }

  #pragma unroll 2
  for (int it = 0; it < 8; ++it) {
    int i = tid + it*512;
    int r = i >> 5, q = i & 31;
    int n = row0 + r;
    float4 v = make_float4(0,0,0,0), g = v;
    if (n < NN) {
      v = reinterpret_cast<const float4*>(node)[(size_t)n*32 + q];
      g = reinterpret_cast<const float4*>(graph)[(size_t)n*32 + q];
    }
    u32 off = (u32)r*272 + (u32)q*8;
    *reinterpret_cast<uint2*>(smx + A_HH + off) = make_uint2(pack_bf16(v.x,v.y), pack_bf16(v.z,v.w));
    float lx=v.x-__bfloat162float(__float2bfloat16(v.x)), ly=v.y-__bfloat162float(__float2bfloat16(v.y));
    float lz=v.z-__bfloat162float(__float2bfloat16(v.z)), lw=v.w-__bfloat162float(__float2bfloat16(v.w));
    *reinterpret_cast<uint2*>(smx + A_HL + off) = make_uint2(pack_bf16(lx,ly), pack_bf16(lz,lw));
    *reinterpret_cast<uint2*>(smx + A_UH + off) = make_uint2(pack_bf16(g.x,g.y), pack_bf16(g.z,g.w));
    lx=g.x-__bfloat162float(__float2bfloat16(g.x)); ly=g.y-__bfloat162float(__float2bfloat16(g.y));
    lz=g.z-__bfloat162float(__float2bfloat16(g.z)); lw=g.w-__bfloat162float(__float2bfloat16(g.w));
    *reinterpret_cast<uint2*>(smx + A_UL + off) = make_uint2(pack_bf16(lx,ly), pack_bf16(lz,lw));
  }

  float acc[2][4][4];

  // h = lrelu(node@Wn + bn)
  ZB4(acc);
  loadW(2, smx, A_W0, A_W1, tid, 512);
  hpass3(sbase+A_HH, sbase+A_HL, w0, w1, acc, mbase, nbase, lane);
  __syncthreads();
  #pragma unroll
  for (int mt=0; mt<2; ++mt)
    #pragma unroll
    for (int hr=0; hr<2; ++hr) {
      int row = mbase + mt*16 + qrow + hr*8;
      #pragma unroll
      for (int nt=0; nt<4; ++nt) {
        int c = nbase + nt*8 + qcol*2;
        float f0 = lrelu(acc[mt][nt][hr*2] + sBn[c]);
        float f1 = lrelu(acc[mt][nt][hr*2+1] + sBn[c+1]);
        __nv_bfloat16 h0=__float2bfloat16(f0), h1=__float2bfloat16(f1);
        u32 off = (u32)row*272 + (u32)c*2;
        *reinterpret_cast<u32*>(smx + A_HH + off) = ((u32)__bfloat16_as_ushort(h1)<<16)|__bfloat16_as_ushort(h0);
        *reinterpret_cast<u32*>(smx + A_HL + off) = pack_bf16(f0-__bfloat162float(h0), f1-__bfloat162float(h1));
      }
    }

  // u = lrelu(graph@Wg + bg)
  ZB4(acc);
  loadW(3, smx, A_W0, A_W1, tid, 512);
  hpass3(sbase+A_UH, sbase+A_UL, w0, w1, acc, mbase, nbase, lane);
  __syncthreads();
  #pragma unroll
  for (int mt=0; mt<2; ++mt)
    #pragma unroll
    for (int hr=0; hr<2; ++hr) {
      int row = mbase + mt*16 + qrow + hr*8;
      #pragma unroll
      for (int nt=0; nt<4; ++nt) {
        int c = nbase + nt*8 + qcol*2;
        float f0 = lrelu(acc[mt][nt][hr*2] + sBg[c]);
        float f1 = lrelu(acc[mt][nt][hr*2+1] + sBg[c+1]);
        __nv_bfloat16 h0=__float2bfloat16(f0), h1=__float2bfloat16(f1);
        u32 off = (u32)row*272 + (u32)c*2;
        *reinterpret_cast<u32*>(smx + A_UH + off) = ((u32)__bfloat16_as_ushort(h1)<<16)|__bfloat16_as_ushort(h0);
        *reinterpret_cast<u32*>(smx + A_UL + off) = pack_bf16(f0-__bfloat162float(h0), f1-__bfloat162float(h1));
      }
    }

  // aterm = h@Weu1
  ZB4(acc);
  loadW(4, smx, A_W0, A_W1, tid, 512);
  hpass3(sbase+A_HH, sbase+A_HL, w0, w1, acc, mbase, nbase, lane);
  #pragma unroll
  for (int mt=0; mt<2; ++mt)
    #pragma unroll
    for (int hr=0; hr<2; ++hr) {
      int row = mbase + mt*16 + qrow + hr*8;
      int n = row0 + row; if (n >= NN) continue;
      #pragma unroll
      for (int nt=0; nt<4; ++nt) {
        int c = nbase + nt*8 + qcol*2;
        *reinterpret_cast<float2*>(d_aterm + (size_t)n*DD + c) =
          make_float2(acc[mt][nt][hr*2], acc[mt][nt][hr*2+1]);
      }
    }

  // bterm = h@Weu2 + u@Weu4 + beu
  ZB4(acc);
  loadW(5, smx, A_W0, A_W1, tid, 512);
  hpass3(sbase+A_HH, sbase+A_HL, w0, w1, acc, mbase, nbase, lane);
  loadW(6, smx, A_W0, A_W1, tid, 512);
  hpass3(sbase+A_UH, sbase+A_UL, w0, w1, acc, mbase, nbase, lane);
  #pragma unroll
  for (int mt=0; mt<2; ++mt)
    #pragma unroll
    for (int hr=0; hr<2; ++hr) {
      int row = mbase + mt*16 + qrow + hr*8;
      int n = row0 + row; if (n >= NN) continue;
      #pragma unroll
      for (int nt=0; nt<4; ++nt) {
        int c = nbase + nt*8 + qcol*2;
        *reinterpret_cast<float2*>(d_bterm + (size_t)n*DD + c) =
          make_float2(acc[mt][nt][hr*2] + sBeu[c], acc[mt][nt][hr*2+1] + sBeu[c+1]);
      }
    }

  // c1 = h@Wnu1 + u@Wnu3 + bnu
  ZB4(acc);
  loadW(7, smx, A_W0, A_W1, tid, 512);
  hpass3(sbase+A_HH, sbase+A_HL, w0, w1, acc, mbase, nbase, lane);
  loadW(8, smx, A_W0, A_W1, tid, 512);
  hpass3(sbase+A_UH, sbase+A_UL, w0, w1, acc, mbase, nbase, lane);
  #pragma unroll
  for (int mt=0; mt<2; ++mt)
    #pragma unroll
    for (int hr=0; hr<2; ++hr) {
      int row = mbase + mt*16 + qrow + hr*8;
      int n = row0 + row; if (n >= NN) continue;
      #pragma unroll
      for (int nt=0; nt<4; ++nt) {
        int c = nbase + nt*8 + qcol*2;
        *reinterpret_cast<float2*>(d_c1 + (size_t)n*DD + c) =
          make_float2(acc[mt][nt][hr*2] + sBnu[c], acc[mt][nt][hr*2+1] + sBnu[c+1]);
      }
    }
}

// ---- kB: 64-edge tiles, 256 threads, residual kept in registers ----
#define B_AH 0
#define B_AL TB64
#define B_WH (2*TB64)
#define B_WL (2*TB64 + TB)
#define B_BE (2*TB64 + 2*TB)
#define B_SRC (B_BE + 512)
#define B_DST (B_SRC + 256)
#define SMB_T (B_DST + 256)

__global__ __launch_bounds__(256) void kB(
    const float* __restrict__ edge, const int* __restrict__ src, const int* __restrict__ dst,
    const float* __restrict__ be, float* __restrict__ out_edge)
{
  extern __shared__ __align__(16) char smx[];
  float* sBe = (float*)(smx + B_BE);
  int* sSrc = (int*)(smx + B_SRC);
  int* sDst = (int*)(smx + B_DST);
  u32 sbase = smaddr(smx);

  int tid = threadIdx.x, lane = tid & 31, wid = tid >> 5;
  int mbase = (wid & 1)*32, nbase = (wid >> 1)*32;
  long row0 = (long)blockIdx.x * 64;
  int qrow = lane >> 2, qcol = lane & 3;

  if (tid < DD) sBe[tid] = be[tid];
  if (tid < 64) { sSrc[tid] = src[row0 + tid]; sDst[tid] = dst[row0 + tid]; }

  for (int i = tid; i < DD*WST/8; i += 256) {
    reinterpret_cast<uint4*>(smx + B_WH)[i] = reinterpret_cast<const uint4*>(d_wth[0])[i];
    reinterpret_cast<uint4*>(smx + B_WL)[i] = reinterpret_cast<const uint4*>(d_wtl[0])[i];
  }
  #pragma unroll 2
  for (int it = 0; it < 8; ++it) {
    int i = tid + it*256;
    int r = i >> 5, q = i & 31;
    float4 v = reinterpret_cast<const float4*>(edge)[row0*32 + i];
    u32 off = (u32)r*272 + (u32)q*8;
    *reinterpret_cast<uint2*>(smx + B_AH + off) = make_uint2(pack_bf16(v.x,v.y), pack_bf16(v.z,v.w));
    float lx=v.x-__bfloat162float(__float2bfloat16(v.x)), ly=v.y-__bfloat162float(__float2bfloat16(v.y));
    float lz=v.z-__bfloat162float(__float2bfloat16(v.z)), lw=v.w-__bfloat162float(__float2bfloat16(v.w));
    *reinterpret_cast<uint2*>(smx + B_AL + off) = make_uint2(pack_bf16(lx,ly), pack_bf16(lz,lw));
  }
  __syncthreads();

  float acc[2][4][4];

  ZB4(acc);
  hpass3(sbase+B_AH, sbase+B_AL, sbase+B_WH, sbase+B_WL, acc, mbase, nbase, lane);
  __syncthreads();

  // epilogue 1: capture residual (e ≈ hi+lo) into regs, then f -> A tiles
  float2 eres[2][2][4];
  #pragma unroll
  for (int mt=0; mt<2; ++mt)
    #pragma unroll
    for (int hr=0; hr<2; ++hr) {
      int row = mbase + mt*16 + qrow + hr*8;
      #pragma unroll
      for (int nt=0; nt<4; ++nt) {
        int c = nbase + nt*8 + qcol*2;
        u32 off = (u32)row*272 + (u32)c*2;
        u32 hh = *reinterpret_cast<u32*>(smx + B_AH + off);
        u32 ll = *reinterpret_cast<u32*>(smx + B_AL + off);
        eres[mt][hr][nt] = make_float2(
          __bfloat162float(__ushort_as_bfloat16((u16)hh)) + __bfloat162float(__ushort_as_bfloat16((u16)ll)),
          __bfloat162float(__ushort_as_bfloat16((u16)(hh>>16))) + __bfloat162float(__ushort_as_bfloat16((u16)(ll>>16))));
        float f0 = lrelu(acc[mt][nt][hr*2] + sBe[c]);
        float f1 = lrelu(acc[mt][nt][hr*2+1] + sBe[c+1]);
        __nv_bfloat16 h0=__float2bfloat16(f0), h1=__float2bfloat16(f1);
        *reinterpret_cast<u32*>(smx + B_AH + off) = ((u32)__bfloat16_as_ushort(h1)<<16)|__bfloat16_as_ushort(h0);
        *reinterpret_cast<u32*>(smx + B_AL + off) = pack_bf16(f0-__bfloat162float(h0), f1-__bfloat162float(h1));
      }
    }
  for (int i = tid; i < DD*WST/8; i += 256) {
    reinterpret_cast<uint4*>(smx + B_WH)[i] = reinterpret_cast<const uint4*>(d_wth[1])[i];
    reinterpret_cast<uint4*>(smx + B_WL)[i] = reinterpret_cast<const uint4*>(d_wtl[1])[i];
  }
  __syncthreads();

  ZB4(acc);
  hpass3(sbase+B_AH, sbase+B_AL, sbase+B_WH, sbase+B_WL, acc, mbase, nbase, lane);

  // final epilogue: residual from registers, gathers batched
  #pragma unroll
  for (int mt=0; mt<2; ++mt)
    #pragma unroll
    for (int hr=0; hr<2; ++hr) {
      int row = mbase + mt*16 + qrow + hr*8;
      long e = row0 + row;
      int s = sSrc[row], d = sDst[row];
      float2 a2[4], b2[4];
      #pragma unroll
      for (int nt=0; nt<4; ++nt) {
        int c = nbase + nt*8 + qcol*2;
        a2[nt] = *reinterpret_cast<const float2*>(d_aterm + (size_t)s*DD + c);
        b2[nt] = *reinterpret_cast<const float2*>(d_bterm + (size_t)d*DD + c);
      }
      #pragma unroll
      for (int nt=0; nt<4; ++nt) {
        int c = nbase + nt*8 + qcol*2;
        float f0 = lrelu(acc[mt][nt][hr*2]   + a2[nt].x + b2[nt].x);
        float f1 = lrelu(acc[mt][nt][hr*2+1] + a2[nt].y + b2[nt].y);
        *reinterpret_cast<float2*>(out_edge + (size_t)e*DD + c) =
          make_float2(f0 + eres[mt][hr][nt].x, f1 + eres[mt][hr][nt].y);
        red2(d_hfsum + (size_t)d*DD + c, f0, f1);
      }
    }
}

// ---- kC: node update + pooling (SIMT, R13) ----
__global__ __launch_bounds__(256) void kC(
    const float* __restrict__ node, const float* __restrict__ graph,
    const int* __restrict__ n2g, const float* __restrict__ Wnu,
    float* __restrict__ out_node)
{
  extern __shared__ float sm[];
  float* Hf = sm; float* Bs = sm + 64*DD;
  int*   sG = reinterpret_cast<int*>(sm + 80*DD);
  float* sD = sm + 80*DD + 64;
  int tid = threadIdx.x, tx = tid & 15, ty = tid >> 4;
  int row0 = blockIdx.x * 64, c0 = tx*4, cB = 64 + tx*4;

  for (int i = tid; i < 64*32; i += 256) {
    int n = row0 + (i >> 5), q = i & 31;
    float4 v = make_float4(0,0,0,0);
    if (n < NN) v = reinterpret_cast<const float4*>(d_hfsum)[(size_t)n*32 + q];
    reinterpret_cast<float4*>(Hf)[i] = v;
  }
  if (tid < 64) {
    int n = row0 + tid, g = 0, dg = 0;
    if (n < NN) { g = n2g[n]; dg = d_deg[n]; atomicAdd(&d_necnt[g], dg); }
    sG[tid] = g;
    sD[tid] = 1.f / fmaxf((float)dg, 1.f);
  }
  __syncthreads();

  #pragma unroll
  for (int i=0;i<4;i++){
    int r = ty*4+i, n = row0 + r; if (n >= NN) continue;
    int g = sG[r];
    float4 h0 = reinterpret_cast<float4*>(Hf)[r*32 + tx];
    float4 h1 = reinterpret_cast<float4*>(Hf)[r*32 + 16 + tx];
    red4(d_epool + g*DD + c0, h0);
    red4(d_epool + g*DD + cB, h1);
    float4 g0 = reinterpret_cast<const float4*>(graph)[(size_t)n*32 + tx];
    float4 g1 = reinterpret_cast<const float4*>(graph)[(size_t)n*32 + 16 + tx];
    red4(d_gpool + g*DD + c0, g0);
    red4(d_gpool + g*DD + cB, g1);
    float rd = sD[r];
    h0.x*=rd; h0.y*=rd; h0.z*=rd; h0.w*=rd;
    h1.x*=rd; h1.y*=rd; h1.z*=rd; h1.w*=rd;
    reinterpret_cast<float4*>(Hf)[r*32 + tx] = h0;
    reinterpret_cast<float4*>(Hf)[r*32 + 16 + tx] = h1;
  }

  u64 acc[4][4];
  ZACC4(acc); mm_pass(Hf, Wnu + 128*DD, acc, Bs, ty, tx, tid);

  #pragma unroll
  for (int i=0;i<4;i++){
    int r = ty*4+i, n = row0 + r; if (n >= NN) continue;
    float v[8]; unpack_acc(acc[i], v);
    const float* cr = d_c1 + (size_t)n*DD;
    float f0=lrelu(v[0]+cr[c0]),   f1=lrelu(v[1]+cr[c0+1]);
    float f2=lrelu(v[2]+cr[c0+2]), f3=lrelu(v[3]+cr[c0+3]);
    float f4=lrelu(v[4]+cr[cB]),   f5=lrelu(v[5]+cr[cB+1]);
    float f6=lrelu(v[6]+cr[cB+2]), f7=lrelu(v[7]+cr[cB+3]);
    float4 n0 = reinterpret_cast<const float4*>(node)[(size_t)n*32 + tx];
    float4 n1 = reinterpret_cast<const float4*>(node)[(size_t)n*32 + 16 + tx];
    *reinterpret_cast<float4*>(out_node + (size_t)n*DD + c0) = make_float4(f0+n0.x,f1+n0.y,f2+n0.z,f3+n0.w);
    *reinterpret_cast<float4*>(out_node + (size_t)n*DD + cB) = make_float4(f4+n1.x,f5+n1.y,f6+n1.z,f7+n1.w);
    int g = sG[r];
    red4(d_npool + g*DD + c0, make_float4(f0,f1,f2,f3));
    red4(d_npool + g*DD + cB, make_float4(f4,f5,f6,f7));
  }
}

__global__ void kD(const float* __restrict__ Wnu, const float* __restrict__ bnu){
  __shared__ float sp[3*DD];
  int g = blockIdx.x, j = threadIdx.x;
  float rn = 1.f / fmaxf((float)d_nncnt[g], 1.f);
  float re = 1.f / fmaxf((float)d_necnt[g], 1.f);
  sp[j]      = d_npool[g*DD+j]*rn;
  sp[DD+j]   = d_epool[g*DD+j]*re;
  sp[2*DD+j] = d_gpool[g*DD+j]*rn;
  __syncthreads();
  float a = bnu[j];
  #pragma unroll 4
  for (int k = 0; k < 3*DD; ++k) a = fmaf(sp[k], Wnu[k*DD+j], a);
  d_gnew[g*DD+j] = lrelu(a);
}

__global__ void kE(const float* __restrict__ graph, const int* __restrict__ n2g,
                   float* __restrict__ out_graph){
  int t = blockIdx.x*blockDim.x + threadIdx.x;
  if (t >= NN*32) return;
  int n = t >> 5, q = t & 31;
  int g = n2g[n];
  float4 gv = reinterpret_cast<const float4*>(d_gnew)[g*32 + q];
  float4 rv = reinterpret_cast<const float4*>(graph)[(size_t)n*32 + q];
  reinterpret_cast<float4*>(out_graph)[t] = make_float4(gv.x+rv.x, gv.y+rv.y, gv.z+rv.z, gv.w+rv.w);
}

extern "C" void kernel_launch(void* const* d_in, const int* in_sizes, int n_in,
                              void* d_out, int out_size) {
  const float* node  = (const float*)d_in[0];
  const float* edge  = (const float*)d_in[1];
  const float* graph = (const float*)d_in[2];
  const int*   src   = (const int*)d_in[3];
  const int*   dst   = (const int*)d_in[4];
  const int*   n2g   = (const int*)d_in[5];
  const float* Wn  = (const float*)d_in[6];
  const float* bn  = (const float*)d_in[7];
  const float* We  = (const float*)d_in[8];
  const float* be  = (const float*)d_in[9];
  const float* Wg  = (const float*)d_in[10];
  const float* bg  = (const float*)d_in[11];
  const float* Weu = (const float*)d_in[12];
  const float* beu = (const float*)d_in[13];
  const float* Wnu = (const float*)d_in[14];
  const float* bnu = (const float*)d_in[15];
  float* out_node  = (float*)d_out;
  float* out_edge  = out_node + (size_t)NN*DD;
  float* out_graph = out_edge + (size_t)EE*DD;

  const int SMC = (80*DD) * 4 + 64*4 + 64*4;
  cudaFuncSetAttribute(kA, cudaFuncAttributeMaxDynamicSharedMemorySize, SMA_T);
  cudaFuncSetAttribute(kB, cudaFuncAttributeMaxDynamicSharedMemorySize, SMB_T);
  cudaFuncSetAttribute(kC, cudaFuncAttributeMaxDynamicSharedMemorySize, SMC);

  kInit<<<(NN*DD + 255)/256, 256>>>();
  kCounts<<<(EE + 255)/256, 256>>>(dst, n2g);
  kW<<<dim3(128, 9), 128>>>(We, Weu, Wn, Wg, Wnu);
  kA<<<(NN + 127)/128, 512, SMA_T>>>(node, graph, bn, bg, beu, bnu);
  kB<<<EE/64, 256, SMB_T>>>(edge, src, dst, be, out_edge);
  kC<<<(NN + 63)/64, 256, SMC>>>(node, graph, n2g, Wnu, out_node);
  kD<<<BB, DD>>>(Wnu, bnu);
  kE<<<(NN*32 + 255)/256, 256>>>(graph, n2g, out_graph);
}

// round 16
// speedup vs baseline: 1.0710x; 1.0411x over previous
#include <cuda_runtime.h>
#include <cuda_bf16.h>

#define NN 50000
#define EE 800000
#define DD 128
#define BB 100
#define LSLOPE 0.01f
typedef unsigned long long u64;
typedef unsigned int u32;
typedef unsigned short u16;

#define FMA2(d,a,b,c) asm("fma.rn.f32x2 %0, %1, %2, %3;" : "=l"(d) : "l"(a), "l"(b), "l"(c))
#define PACK2(d,x)    asm("mov.b64 %0, {%1, %1};" : "=l"(d) : "r"(__float_as_uint(x)))
#define UNPK2(lo,hi,v) asm("mov.b64 {%0, %1}, %2;" : "=r"(lo), "=r"(hi) : "l"(v))

#define LDSM4(r0,r1,r2,r3,a) \
  asm volatile("ldmatrix.sync.aligned.m8n8.x4.shared.b16 {%0,%1,%2,%3}, [%4];" \
    : "=r"(r0),"=r"(r1),"=r"(r2),"=r"(r3) : "r"(a))

#define MMA16816(c, a0,a1,a2,a3, b0,b1) \
  asm volatile("mma.sync.aligned.m16n8k16.row.col.f32.bf16.bf16.f32 " \
    "{%0,%1,%2,%3}, {%4,%5,%6,%7}, {%8,%9}, {%0,%1,%2,%3};" \
    : "+f"((c)[0]),"+f"((c)[1]),"+f"((c)[2]),"+f"((c)[3]) \
    : "r"(a0),"r"(a1),"r"(a2),"r"(a3), "r"(b0),"r"(b1))

#define WST 136
#define TB  34816

// ---------------- scratch ----------------
__device__ float d_aterm[NN*DD];
__device__ float d_bterm[NN*DD];
__device__ float d_c1[NN*DD];
__device__ float d_hfsum[NN*DD];
__device__ float d_npool[BB*DD];
__device__ float d_epool[BB*DD];
__device__ float d_gpool[BB*DD];
__device__ float d_gnew[BB*DD];
__device__ int   d_deg[NN];
__device__ int   d_nncnt[BB];
__device__ int   d_necnt[BB];
// 0=We 1=Weu3 2=Wn 3=Wg 4=Weu1 5=Weu2 6=Weu4 7=Wnu1 8=Wnu3
__device__ __align__(16) u16 d_wth[9][DD*WST];
__device__ __align__(16) u16 d_wtl[9][DD*WST];

__device__ __forceinline__ float lrelu(float x){ return x > 0.f ? x : LSLOPE*x; }

__device__ __forceinline__ void red4(float* p, float4 v){
  asm volatile("red.global.add.v4.f32 [%0], {%1, %2, %3, %4};"
               :: "l"(p), "f"(v.x), "f"(v.y), "f"(v.z), "f"(v.w) : "memory");
}
__device__ __forceinline__ void red2(float* p, float x, float y){
  asm volatile("red.global.add.v2.f32 [%0], {%1, %2};"
               :: "l"(p), "f"(x), "f"(y) : "memory");
}
__device__ __forceinline__ u32 smaddr(const void* p){
  u32 a; asm("{ .reg .u64 t; cvta.to.shared.u64 t, %1; cvt.u32.u64 %0, t; }" : "=r"(a) : "l"(p));
  return a;
}
__device__ __forceinline__ u32 pack_bf16(float a, float b){
  __nv_bfloat16 h0=__float2bfloat16(a), h1=__float2bfloat16(b);
  return ((u32)__bfloat16_as_ushort(h1)<<16)|__bfloat16_as_ushort(h0);
}
__device__ __forceinline__ void unpack_acc(const u64* a, float* v){
  unsigned lo, hi;
  UNPK2(lo,hi,a[0]); v[0]=__uint_as_float(lo); v[1]=__uint_as_float(hi);
  UNPK2(lo,hi,a[1]); v[2]=__uint_as_float(lo); v[3]=__uint_as_float(hi);
  UNPK2(lo,hi,a[2]); v[4]=__uint_as_float(lo); v[5]=__uint_as_float(hi);
  UNPK2(lo,hi,a[3]); v[6]=__uint_as_float(lo); v[7]=__uint_as_float(hi);
}
#define ZACC4(acc) { _Pragma("unroll") for (int zi=0; zi<4; ++zi){ _Pragma("unroll") for (int zj=0; zj<4; ++zj) acc[zi][zj]=0ull; } }
#define ZB4(acc) { _Pragma("unroll") for (int za=0; za<2; ++za) _Pragma("unroll") for (int zb=0; zb<4; ++zb) _Pragma("unroll") for (int zc=0; zc<4; ++zc) acc[za][zb][zc]=0.f; }

// FUSED 3-split pass: acc += AH@BH + AH@BL + AL@BH (2 m-tiles x 4 n-tiles per warp)
__device__ __forceinline__ void hpass3(u32 aH, u32 aL, u32 bH, u32 bL,
                                       float acc[2][4][4], int mbase, int nbase, int lane)
{
  int at = lane >> 3;
  int arow = (at & 1)*8 + (lane & 7);
  int acol = (at >> 1)*8;
  int bg = lane >> 3;
  int bn = (bg >> 1)*8 + (lane & 7);
  int bk = (bg & 1)*8;
  #pragma unroll
  for (int ks = 0; ks < 8; ++ks) {
    int k0 = ks*16;
    u32 ah[2][4], al[2][4];
    #pragma unroll
    for (int mt = 0; mt < 2; ++mt) {
      u32 off = (u32)(mbase + mt*16 + arow)*272 + (u32)(k0 + acol)*2;
      LDSM4(ah[mt][0],ah[mt][1],ah[mt][2],ah[mt][3], aH + off);
      LDSM4(al[mt][0],al[mt][1],al[mt][2],al[mt][3], aL + off);
    }
    u32 bh[4][2], bl[4][2];
    #pragma unroll
    for (int g = 0; g < 2; ++g) {
      u32 off = (u32)(nbase + g*16 + bn)*272 + (u32)(k0 + bk)*2;
      u32 r0,r1,r2,r3;
      LDSM4(r0,r1,r2,r3, bH + off);
      bh[g*2][0]=r0; bh[g*2][1]=r1; bh[g*2+1][0]=r2; bh[g*2+1][1]=r3;
      LDSM4(r0,r1,r2,r3, bL + off);
      bl[g*2][0]=r0; bl[g*2][1]=r1; bl[g*2+1][0]=r2; bl[g*2+1][1]=r3;
    }
    #pragma unroll
    for (int mt = 0; mt < 2; ++mt)
      #pragma unroll
      for (int nt = 0; nt < 4; ++nt) {
        MMA16816(acc[mt][nt], ah[mt][0],ah[mt][1],ah[mt][2],ah[mt][3], bh[nt][0],bh[nt][1]);
        MMA16816(acc[mt][nt], ah[mt][0],ah[mt][1],ah[mt][2],ah[mt][3], bl[nt][0],bl[nt][1]);
        MMA16816(acc[mt][nt], al[mt][0],al[mt][1],al[mt][2],al[mt][3], bh[nt][0],bh[nt][1]);
      }
  }
}

__device__ __forceinline__ void loadW(int widx, char* smx, int dH, int dL, int tid, int nthr){
  __syncthreads();
  for (int i = tid; i < DD*WST/8; i += nthr) {
    reinterpret_cast<uint4*>(smx + dH)[i] = reinterpret_cast<const uint4*>(d_wth[widx])[i];
    reinterpret_cast<uint4*>(smx + dL)[i] = reinterpret_cast<const uint4*>(d_wtl[widx])[i];
  }
  __syncthreads();
}

// SIMT 64-row GEMM (kC)
__device__ __forceinline__ void mm_pass(const float* As, const float* __restrict__ W,
                                        u64 acc[4][4], float* Bs, int ty, int tx, int tid)
{
  #pragma unroll 1
  for (int k0 = 0; k0 < 128; k0 += 16) {
    __syncthreads();
    { int kr = tid >> 4, cc = (tid & 15) << 3;
      const float4* s4 = reinterpret_cast<const float4*>(W + (k0 + kr)*DD + cc);
      float4* t4 = reinterpret_cast<float4*>(Bs + kr*DD + cc);
      t4[0] = s4[0]; t4[1] = s4[1];
    }
    __syncthreads();
    #pragma unroll 4
    for (int k = 0; k < 16; ++k) {
      const float* br = Bs + k*DD;
      u64 b0 = *reinterpret_cast<const u64*>(br + tx*4);
      u64 b1 = *reinterpret_cast<const u64*>(br + tx*4 + 2);
      u64 b2 = *reinterpret_cast<const u64*>(br + 64 + tx*4);
      u64 b3 = *reinterpret_cast<const u64*>(br + 64 + tx*4 + 2);
      #pragma unroll
      for (int i = 0; i < 4; ++i) {
        u64 aa; PACK2(aa, As[(ty*4 + i)*DD + k0 + k]);
        FMA2(acc[i][0], aa, b0, acc[i][0]);
        FMA2(acc[i][1], aa, b1, acc[i][1]);
        FMA2(acc[i][2], aa, b2, acc[i][2]);
        FMA2(acc[i][3], aa, b3, acc[i][3]);
      }
    }
  }
}

__global__ void kInit(){
  int idx = blockIdx.x*blockDim.x + threadIdx.x;
  if (idx < NN*DD) d_hfsum[idx] = 0.f;
  if (idx < BB*DD) { d_npool[idx]=0.f; d_epool[idx]=0.f; d_gpool[idx]=0.f; }
  if (idx < NN) d_deg[idx] = 0;
  if (idx < BB) { d_nncnt[idx]=0; d_necnt[idx]=0; }
}

__global__ void kCounts(const int* __restrict__ dst, const int* __restrict__ n2g){
  int idx = blockIdx.x*blockDim.x + threadIdx.x;
  if (idx < EE) atomicAdd(&d_deg[dst[idx]], 1);
  if (idx < NN) atomicAdd(&d_nncnt[n2g[idx]], 1);
}

__global__ void kW(const float* __restrict__ We, const float* __restrict__ Weu,
                   const float* __restrict__ Wn, const float* __restrict__ Wg,
                   const float* __restrict__ Wnu){
  int k = blockIdx.x, w = blockIdx.y, n = threadIdx.x;
  const float* src;
  switch (w) {
    case 0: src = We; break;
    case 1: src = Weu + 256*DD; break;
    case 2: src = Wn; break;
    case 3: src = Wg; break;
    case 4: src = Weu; break;
    case 5: src = Weu + 128*DD; break;
    case 6: src = Weu + 384*DD; break;
    case 7: src = Wnu; break;
    default: src = Wnu + 256*DD; break;
  }
  float v = src[k*DD + n];
  __nv_bfloat16 hi = __float2bfloat16(v);
  __nv_bfloat16 lo = __float2bfloat16(v - __bfloat162float(hi));
  d_wth[w][n*WST + k] = __bfloat16_as_ushort(hi);
  d_wtl[w][n*WST + k] = __bfloat16_as_ushort(lo);
}

// ---- kA: fused HMMA per-node precompute (512 threads, dual weight buffers) ----
#define A_HH 0
#define A_HL TB
#define A_UH (2*TB)
#define A_UL (3*TB)
#define A_W0 (4*TB)
#define A_W1 (5*TB)
#define A_BI (6*TB)
#define SMA_T (6*TB + 2048)

__global__ __launch_bounds__(512, 1) void kA(
    const float* __restrict__ node, const float* __restrict__ graph,
    const float* __restrict__ bn, const float* __restrict__ bg,
    const float* __restrict__ beu, const float* __restrict__ bnu)
{
  extern __shared__ __align__(16) char smx[];
  float* sBn  = (float*)(smx + A_BI);
  float* sBg  = sBn + DD;
  float* sBeu = sBg + DD;
  float* sBnu = sBeu + DD;
  u32 sbase = smaddr(smx);
  int tid = threadIdx.x, lane = tid & 31, wid = tid >> 5;
  int mbase = (wid & 3)*32, nbase = (wid >> 2)*32;
  int row0 = blockIdx.x * 128;
  int qrow = lane >> 2, qcol = lane & 3;
  u32 w0 = sbase + A_W0, w1 = sbase + A_W1;

  if (tid < DD) { sBn[tid]=bn[tid]; sBg[tid]=bg[tid]; sBeu[tid]=beu[tid]; sBnu[tid]=bnu[tid]; }

  #pragma unroll 2
  for (int it = 0; it < 8; ++it) {
    int i = tid + it*512;
    int r = i >> 5, q = i & 31;
    int n = row0 + r;
    float4 v = make_float4(0,0,0,0), g = v;
    if (n < NN) {
      v = reinterpret_cast<const float4*>(node)[(size_t)n*32 + q];
      g = reinterpret_cast<const float4*>(graph)[(size_t)n*32 + q];
    }
    u32 off = (u32)r*272 + (u32)q*8;
    *reinterpret_cast<uint2*>(smx + A_HH + off) = make_uint2(pack_bf16(v.x,v.y), pack_bf16(v.z,v.w));
    float lx=v.x-__bfloat162float(__float2bfloat16(v.x)), ly=v.y-__bfloat162float(__float2bfloat16(v.y));
    float lz=v.z-__bfloat162float(__float2bfloat16(v.z)), lw=v.w-__bfloat162float(__float2bfloat16(v.w));
    *reinterpret_cast<uint2*>(smx + A_HL + off) = make_uint2(pack_bf16(lx,ly), pack_bf16(lz,lw));
    *reinterpret_cast<uint2*>(smx + A_UH + off) = make_uint2(pack_bf16(g.x,g.y), pack_bf16(g.z,g.w));
    lx=g.x-__bfloat162float(__float2bfloat16(g.x)); ly=g.y-__bfloat162float(__float2bfloat16(g.y));
    lz=g.z-__bfloat162float(__float2bfloat16(g.z)); lw=g.w-__bfloat162float(__float2bfloat16(g.w));
    *reinterpret_cast<uint2*>(smx + A_UL + off) = make_uint2(pack_bf16(lx,ly), pack_bf16(lz,lw));
  }

  float acc[2][4][4];

  // h = lrelu(node@Wn + bn)
  ZB4(acc);
  loadW(2, smx, A_W0, A_W1, tid, 512);
  hpass3(sbase+A_HH, sbase+A_HL, w0, w1, acc, mbase, nbase, lane);
  __syncthreads();
  #pragma unroll
  for (int mt=0; mt<2; ++mt)
    #pragma unroll
    for (int hr=0; hr<2; ++hr) {
      int row = mbase + mt*16 + qrow + hr*8;
      #pragma unroll
      for (int nt=0; nt<4; ++nt) {
        int c = nbase + nt*8 + qcol*2;
        float f0 = lrelu(acc[mt][nt][hr*2] + sBn[c]);
        float f1 = lrelu(acc[mt][nt][hr*2+1] + sBn[c+1]);
        __nv_bfloat16 h0=__float2bfloat16(f0), h1=__float2bfloat16(f1);
        u32 off = (u32)row*272 + (u32)c*2;
        *reinterpret_cast<u32*>(smx + A_HH + off) = ((u32)__bfloat16_as_ushort(h1)<<16)|__bfloat16_as_ushort(h0);
        *reinterpret_cast<u32*>(smx + A_HL + off) = pack_bf16(f0-__bfloat162float(h0), f1-__bfloat162float(h1));
      }
    }

  // u = lrelu(graph@Wg + bg)
  ZB4(acc);
  loadW(3, smx, A_W0, A_W1, tid, 512);
  hpass3(sbase+A_UH, sbase+A_UL, w0, w1, acc, mbase, nbase, lane);
  __syncthreads();
  #pragma unroll
  for (int mt=0; mt<2; ++mt)
    #pragma unroll
    for (int hr=0; hr<2; ++hr) {
      int row = mbase + mt*16 + qrow + hr*8;
      #pragma unroll
      for (int nt=0; nt<4; ++nt) {
        int c = nbase + nt*8 + qcol*2;
        float f0 = lrelu(acc[mt][nt][hr*2] + sBg[c]);
        float f1 = lrelu(acc[mt][nt][hr*2+1] + sBg[c+1]);
        __nv_bfloat16 h0=__float2bfloat16(f0), h1=__float2bfloat16(f1);
        u32 off = (u32)row*272 + (u32)c*2;
        *reinterpret_cast<u32*>(smx + A_UH + off) = ((u32)__bfloat16_as_ushort(h1)<<16)|__bfloat16_as_ushort(h0);
        *reinterpret_cast<u32*>(smx + A_UL + off) = pack_bf16(f0-__bfloat162float(h0), f1-__bfloat162float(h1));
      }
    }

  // aterm = h@Weu1
  ZB4(acc);
  loadW(4, smx, A_W0, A_W1, tid, 512);
  hpass3(sbase+A_HH, sbase+A_HL, w0, w1, acc, mbase, nbase, lane);
  #pragma unroll
  for (int mt=0; mt<2; ++mt)
    #pragma unroll
    for (int hr=0; hr<2; ++hr) {
      int row = mbase + mt*16 + qrow + hr*8;
      int n = row0 + row; if (n >= NN) continue;
      #pragma unroll
      for (int nt=0; nt<4; ++nt) {
        int c = nbase + nt*8 + qcol*2;
        *reinterpret_cast<float2*>(d_aterm + (size_t)n*DD + c) =
          make_float2(acc[mt][nt][hr*2], acc[mt][nt][hr*2+1]);
      }
    }

  // bterm = h@Weu2 + u@Weu4 + beu
  ZB4(acc);
  loadW(5, smx, A_W0, A_W1, tid, 512);
  hpass3(sbase+A_HH, sbase+A_HL, w0, w1, acc, mbase, nbase, lane);
  loadW(6, smx, A_W0, A_W1, tid, 512);
  hpass3(sbase+A_UH, sbase+A_UL, w0, w1, acc, mbase, nbase, lane);
  #pragma unroll
  for (int mt=0; mt<2; ++mt)
    #pragma unroll
    for (int hr=0; hr<2; ++hr) {
      int row = mbase + mt*16 + qrow + hr*8;
      int n = row0 + row; if (n >= NN) continue;
      #pragma unroll
      for (int nt=0; nt<4; ++nt) {
        int c = nbase + nt*8 + qcol*2;
        *reinterpret_cast<float2*>(d_bterm + (size_t)n*DD + c) =
          make_float2(acc[mt][nt][hr*2] + sBeu[c], acc[mt][nt][hr*2+1] + sBeu[c+1]);
      }
    }

  // c1 = h@Wnu1 + u@Wnu3 + bnu
  ZB4(acc);
  loadW(7, smx, A_W0, A_W1, tid, 512);
  hpass3(sbase+A_HH, sbase+A_HL, w0, w1, acc, mbase, nbase, lane);
  loadW(8, smx, A_W0, A_W1, tid, 512);
  hpass3(sbase+A_UH, sbase+A_UL, w0, w1, acc, mbase, nbase, lane);
  #pragma unroll
  for (int mt=0; mt<2; ++mt)
    #pragma unroll
    for (int hr=0; hr<2; ++hr) {
      int row = mbase + mt*16 + qrow + hr*8;
      int n = row0 + row; if (n >= NN) continue;
      #pragma unroll
      for (int nt=0; nt<4; ++nt) {
        int c = nbase + nt*8 + qcol*2;
        *reinterpret_cast<float2*>(d_c1 + (size_t)n*DD + c) =
          make_float2(acc[mt][nt][hr*2] + sBnu[c], acc[mt][nt][hr*2+1] + sBnu[c+1]);
      }
    }
}

// ---- kB: PERSISTENT edge kernel (512 threads, 128-edge tiles, weights resident) ----
#define B_AH 0
#define B_AL TB
#define B_WH1 (2*TB)
#define B_WL1 (3*TB)
#define B_WH2 (4*TB)
#define B_WL2 (5*TB)
#define B_BE  (6*TB)
#define B_SRC (6*TB + 512)
#define B_DST (6*TB + 1024)
#define SMB_T (6*TB + 1536)

__global__ __launch_bounds__(512, 1) void kB(
    const float* __restrict__ edge, const int* __restrict__ src, const int* __restrict__ dst,
    const float* __restrict__ be, float* __restrict__ out_edge)
{
  extern __shared__ __align__(16) char smx[];
  float* sBe = (float*)(smx + B_BE);
  int* sSrc = (int*)(smx + B_SRC);
  int* sDst = (int*)(smx + B_DST);
  u32 sbase = smaddr(smx);

  int tid = threadIdx.x, lane = tid & 31, wid = tid >> 5;
  int mbase = (wid & 3)*32, nbase = (wid >> 2)*32;
  int qrow = lane >> 2, qcol = lane & 3;

  if (tid < DD) sBe[tid] = be[tid];
  // load ALL weights once
  for (int i = tid; i < DD*WST/8; i += 512) {
    reinterpret_cast<uint4*>(smx + B_WH1)[i] = reinterpret_cast<const uint4*>(d_wth[0])[i];
    reinterpret_cast<uint4*>(smx + B_WL1)[i] = reinterpret_cast<const uint4*>(d_wtl[0])[i];
    reinterpret_cast<uint4*>(smx + B_WH2)[i] = reinterpret_cast<const uint4*>(d_wth[1])[i];
    reinterpret_cast<uint4*>(smx + B_WL2)[i] = reinterpret_cast<const uint4*>(d_wtl[1])[i];
  }
  __syncthreads();

  for (int t = blockIdx.x; t < EE/128; t += gridDim.x) {
    long row0 = (long)t * 128;

    if (tid < 128) { sSrc[tid] = src[row0 + tid]; sDst[tid] = dst[row0 + tid]; }
    #pragma unroll 2
    for (int it = 0; it < 8; ++it) {
      int i = tid + it*512;
      int r = i >> 5, q = i & 31;
      float4 v = reinterpret_cast<const float4*>(edge)[row0*32 + i];
      u32 off = (u32)r*272 + (u32)q*8;
      *reinterpret_cast<uint2*>(smx + B_AH + off) = make_uint2(pack_bf16(v.x,v.y), pack_bf16(v.z,v.w));
      float lx=v.x-__bfloat162float(__float2bfloat16(v.x)), ly=v.y-__bfloat162float(__float2bfloat16(v.y));
      float lz=v.z-__bfloat162float(__float2bfloat16(v.z)), lw=v.w-__bfloat162float(__float2bfloat16(v.w));
      *reinterpret_cast<uint2*>(smx + B_AL + off) = make_uint2(pack_bf16(lx,ly), pack_bf16(lz,lw));
    }
    __syncthreads();

    float acc[2][4][4];
    ZB4(acc);
    hpass3(sbase+B_AH, sbase+B_AL, sbase+B_WH1, sbase+B_WL1, acc, mbase, nbase, lane);
    __syncthreads();

    // epilogue 1: capture residual, write f to A tiles
    float2 eres[2][2][4];
    #pragma unroll
    for (int mt=0; mt<2; ++mt)
      #pragma unroll
      for (int hr=0; hr<2; ++hr) {
        int row = mbase + mt*16 + qrow + hr*8;
        #pragma unroll
        for (int nt=0; nt<4; ++nt) {
          int c = nbase + nt*8 + qcol*2;
          u32 off = (u32)row*272 + (u32)c*2;
          u32 hh = *reinterpret_cast<u32*>(smx + B_AH + off);
          u32 ll = *reinterpret_cast<u32*>(smx + B_AL + off);
          eres[mt][hr][nt] = make_float2(
            __bfloat162float(__ushort_as_bfloat16((u16)hh)) + __bfloat162float(__ushort_as_bfloat16((u16)ll)),
            __bfloat162float(__ushort_as_bfloat16((u16)(hh>>16))) + __bfloat162float(__ushort_as_bfloat16((u16)(ll>>16))));
          float f0 = lrelu(acc[mt][nt][hr*2] + sBe[c]);
          float f1 = lrelu(acc[mt][nt][hr*2+1] + sBe[c+1]);
          __nv_bfloat16 h0=__float2bfloat16(f0), h1=__float2bfloat16(f1);
          *reinterpret_cast<u32*>(smx + B_AH + off) = ((u32)__bfloat16_as_ushort(h1)<<16)|__bfloat16_as_ushort(h0);
          *reinterpret_cast<u32*>(smx + B_AL + off) = pack_bf16(f0-__bfloat162float(h0), f1-__bfloat162float(h1));
        }
      }
    __syncthreads();

    ZB4(acc);
    hpass3(sbase+B_AH, sbase+B_AL, sbase+B_WH2, sbase+B_WL2, acc, mbase, nbase, lane);

    // final epilogue
    #pragma unroll
    for (int mt=0; mt<2; ++mt)
      #pragma unroll
      for (int hr=0; hr<2; ++hr) {
        int row = mbase + mt*16 + qrow + hr*8;
        long e = row0 + row;
        int s = sSrc[row], d = sDst[row];
        float2 a2[4], b2[4];
        #pragma unroll
        for (int nt=0; nt<4; ++nt) {
          int c = nbase + nt*8 + qcol*2;
          a2[nt] = *reinterpret_cast<const float2*>(d_aterm + (size_t)s*DD + c);
          b2[nt] = *reinterpret_cast<const float2*>(d_bterm + (size_t)d*DD + c);
        }
        #pragma unroll
        for (int nt=0; nt<4; ++nt) {
          int c = nbase + nt*8 + qcol*2;
          float f0 = lrelu(acc[mt][nt][hr*2]   + a2[nt].x + b2[nt].x);
          float f1 = lrelu(acc[mt][nt][hr*2+1] + a2[nt].y + b2[nt].y);
          *reinterpret_cast<float2*>(out_edge + (size_t)e*DD + c) =
            make_float2(f0 + eres[mt][hr][nt].x, f1 + eres[mt][hr][nt].y);
          red2(d_hfsum + (size_t)d*DD + c, f0, f1);
        }
      }
    __syncthreads();
  }
}

// ---- kC: node update + pooling (SIMT) ----
__global__ __launch_bounds__(256) void kC(
    const float* __restrict__ node, const float* __restrict__ graph,
    const int* __restrict__ n2g, const float* __restrict__ Wnu,
    float* __restrict__ out_node)
{
  extern __shared__ float sm[];
  float* Hf = sm; float* Bs = sm + 64*DD;
  int*   sG = reinterpret_cast<int*>(sm + 80*DD);
  float* sD = sm + 80*DD + 64;
  int tid = threadIdx.x, tx = tid & 15, ty = tid >> 4;
  int row0 = blockIdx.x * 64, c0 = tx*4, cB = 64 + tx*4;

  for (int i = tid; i < 64*32; i += 256) {
    int n = row0 + (i >> 5), q = i & 31;
    float4 v = make_float4(0,0,0,0);
    if (n < NN) v = reinterpret_cast<const float4*>(d_hfsum)[(size_t)n*32 + q];
    reinterpret_cast<float4*>(Hf)[i] = v;
  }
  if (tid < 64) {
    int n = row0 + tid, g = 0, dg = 0;
    if (n < NN) { g = n2g[n]; dg = d_deg[n]; atomicAdd(&d_necnt[g], dg); }
    sG[tid] = g;
    sD[tid] = 1.f / fmaxf((float)dg, 1.f);
  }
  __syncthreads();

  #pragma unroll
  for (int i=0;i<4;i++){
    int r = ty*4+i, n = row0 + r; if (n >= NN) continue;
    int g = sG[r];
    float4 h0 = reinterpret_cast<float4*>(Hf)[r*32 + tx];
    float4 h1 = reinterpret_cast<float4*>(Hf)[r*32 + 16 + tx];
    red4(d_epool + g*DD + c0, h0);
    red4(d_epool + g*DD + cB, h1);
    float4 g0 = reinterpret_cast<const float4*>(graph)[(size_t)n*32 + tx];
    float4 g1 = reinterpret_cast<const float4*>(graph)[(size_t)n*32 + 16 + tx];
    red4(d_gpool + g*DD + c0, g0);
    red4(d_gpool + g*DD + cB, g1);
    float rd = sD[r];
    h0.x*=rd; h0.y*=rd; h0.z*=rd; h0.w*=rd;
    h1.x*=rd; h1.y*=rd; h1.z*=rd; h1.w*=rd;
    reinterpret_cast<float4*>(Hf)[r*32 + tx] = h0;
    reinterpret_cast<float4*>(Hf)[r*32 + 16 + tx] = h1;
  }

  u64 acc[4][4];
  ZACC4(acc); mm_pass(Hf, Wnu + 128*DD, acc, Bs, ty, tx, tid);

  #pragma unroll
  for (int i=0;i<4;i++){
    int r = ty*4+i, n = row0 + r; if (n >= NN) continue;
    float v[8]; unpack_acc(acc[i], v);
    const float* cr = d_c1 + (size_t)n*DD;
    float f0=lrelu(v[0]+cr[c0]),   f1=lrelu(v[1]+cr[c0+1]);
    float f2=lrelu(v[2]+cr[c0+2]), f3=lrelu(v[3]+cr[c0+3]);
    float f4=lrelu(v[4]+cr[cB]),   f5=lrelu(v[5]+cr[cB+1]);
    float f6=lrelu(v[6]+cr[cB+2]), f7=lrelu(v[7]+cr[cB+3]);
    float4 n0 = reinterpret_cast<const float4*>(node)[(size_t)n*32 + tx];
    float4 n1 = reinterpret_cast<const float4*>(node)[(size_t)n*32 + 16 + tx];
    *reinterpret_cast<float4*>(out_node + (size_t)n*DD + c0) = make_float4(f0+n0.x,f1+n0.y,f2+n0.z,f3+n0.w);
    *reinterpret_cast<float4*>(out_node + (size_t)n*DD + cB) = make_float4(f4+n1.x,f5+n1.y,f6+n1.z,f7+n1.w);
    int g = sG[r];
    red4(d_npool + g*DD + c0, make_float4(f0,f1,f2,f3));
    red4(d_npool + g*DD + cB, make_float4(f4,f5,f6,f7));
  }
}

__global__ void kD(const float* __restrict__ Wnu, const float* __restrict__ bnu){
  __shared__ float sp[3*DD];
  int g = blockIdx.x, j = threadIdx.x;
  float rn = 1.f / fmaxf((float)d_nncnt[g], 1.f);
  float re = 1.f / fmaxf((float)d_necnt[g], 1.f);
  sp[j]      = d_npool[g*DD+j]*rn;
  sp[DD+j]   = d_epool[g*DD+j]*re;
  sp[2*DD+j] = d_gpool[g*DD+j]*rn;
  __syncthreads();
  float a = bnu[j];
  #pragma unroll 4
  for (int k = 0; k < 3*DD; ++k) a = fmaf(sp[k], Wnu[k*DD+j], a);
  d_gnew[g*DD+j] = lrelu(a);
}

__global__ void kE(const float* __restrict__ graph, const int* __restrict__ n2g,
                   float* __restrict__ out_graph){
  int t = blockIdx.x*blockDim.x + threadIdx.x;
  if (t >= NN*32) return;
  int n = t >> 5, q = t & 31;
  int g = n2g[n];
  float4 gv = reinterpret_cast<const float4*>(d_gnew)[g*32 + q];
  float4 rv = reinterpret_cast<const float4*>(graph)[(size_t)n*32 + q];
  reinterpret_cast<float4*>(out_graph)[t] = make_float4(gv.x+rv.x, gv.y+rv.y, gv.z+rv.z, gv.w+rv.w);
}

extern "C" void kernel_launch(void* const* d_in, const int* in_sizes, int n_in,
                              void* d_out, int out_size) {
  const float* node  = (const float*)d_in[0];
  const float* edge  = (const float*)d_in[1];
  const float* graph = (const float*)d_in[2];
  const int*   src   = (const int*)d_in[3];
  const int*   dst   = (const int*)d_in[4];
  const int*   n2g   = (const int*)d_in[5];
  const float* Wn  = (const float*)d_in[6];
  const float* bn  = (const float*)d_in[7];
  const float* We  = (const float*)d_in[8];
  const float* be  = (const float*)d_in[9];
  const float* Wg  = (const float*)d_in[10];
  const float* bg  = (const float*)d_in[11];
  const float* Weu = (const float*)d_in[12];
  const float* beu = (const float*)d_in[13];
  const float* Wnu = (const float*)d_in[14];
  const float* bnu = (const float*)d_in[15];
  float* out_node  = (float*)d_out;
  float* out_edge  = out_node + (size_t)NN*DD;
  float* out_graph = out_edge + (size_t)EE*DD;

  const int SMC = (80*DD) * 4 + 64*4 + 64*4;
  cudaFuncSetAttribute(kA, cudaFuncAttributeMaxDynamicSharedMemorySize, SMA_T);
  cudaFuncSetAttribute(kB, cudaFuncAttributeMaxDynamicSharedMemorySize, SMB_T);
  cudaFuncSetAttribute(kC, cudaFuncAttributeMaxDynamicSharedMemorySize, SMC);

  kInit<<<(NN*DD + 255)/256, 256>>>();
  kCounts<<<(EE + 255)/256, 256>>>(dst, n2g);
  kW<<<dim3(128, 9), 128>>>(We, Weu, Wn, Wg, Wnu);
  kA<<<(NN + 127)/128, 512, SMA_T>>>(node, graph, bn, bg, beu, bnu);
  kB<<<148, 512, SMB_T>>>(edge, src, dst, be, out_edge);
  kC<<<(NN + 63)/64, 256, SMC>>>(node, graph, n2g, Wnu, out_node);
  kD<<<BB, DD>>>(Wnu, bnu);
  kE<<<(NN*32 + 255)/256, 256>>>(graph, n2g, out_graph);
}